// round 9
// baseline (speedup 1.0000x reference)
#include <cuda_runtime.h>
#include <cuda_bf16.h>
#include <cstdint>

#define IN_DIM  512
#define OUT_DIM 462
#define BROWS   65536

// ---------------------------------------------------------------------------
// helpers
// ---------------------------------------------------------------------------
__device__ __forceinline__ uint32_t smem_u32(const void* p) {
    uint32_t a;
    asm("{ .reg .u64 t; cvta.to.shared.u64 t, %1; cvt.u32.u64 %0, t; }" : "=r"(a) : "l"(p));
    return a;
}

#define SW128(o) ((o) ^ (((o) >> 3) & 0x70))

#define CPA16(dst, src) \
    asm volatile("cp.async.cg.shared.global [%0], [%1], 16;" :: "r"(dst), "l"(src) : "memory")
#define CPA_COMMIT() asm volatile("cp.async.commit_group;" ::: "memory")
#define CPA_WAIT0()  asm volatile("cp.async.wait_group 0;" ::: "memory")
#define CPA_WAIT1()  asm volatile("cp.async.wait_group 1;" ::: "memory")

__device__ __forceinline__ void ldm_x4(uint32_t* r, uint32_t addr) {
    asm volatile("ldmatrix.sync.aligned.m8n8.x4.shared.b16 {%0,%1,%2,%3}, [%4];"
        : "=r"(r[0]), "=r"(r[1]), "=r"(r[2]), "=r"(r[3]) : "r"(addr));
}
__device__ __forceinline__ void mma_bf16(float* c, const uint32_t* a, const uint32_t* b) {
    asm volatile("mma.sync.aligned.m16n8k16.row.col.f32.bf16.bf16.f32 "
        "{%0,%1,%2,%3}, {%4,%5,%6,%7}, {%8,%9}, {%0,%1,%2,%3};"
        : "+f"(c[0]), "+f"(c[1]), "+f"(c[2]), "+f"(c[3])
        : "r"(a[0]), "r"(a[1]), "r"(a[2]), "r"(a[3]), "r"(b[0]), "r"(b[1]));
}

__device__ __forceinline__ uint32_t pack_hi(float a, float b) {
    __nv_bfloat162 p = __halves2bfloat162(__float2bfloat16_rn(a), __float2bfloat16_rn(b));
    return *reinterpret_cast<uint32_t*>(&p);
}
__device__ __forceinline__ uint32_t pack_lo(float a, float b) {
    __nv_bfloat16 ha = __float2bfloat16_rn(a), hb = __float2bfloat16_rn(b);
    __nv_bfloat162 p = __halves2bfloat162(
        __float2bfloat16_rn(a - __bfloat162float(ha)),
        __float2bfloat16_rn(b - __bfloat162float(hb)));
    return *reinterpret_cast<uint32_t*>(&p);
}

// ---------------------------------------------------------------------------
// Device scratch
// ---------------------------------------------------------------------------
__device__ float          g_sw[IN_DIM];
__device__ __nv_bfloat16  g_whiT[IN_DIM * IN_DIM];   // B[n][k], n>=462 zero
__device__ __nv_bfloat16  g_wloT[IN_DIM * IN_DIM];
__device__ float          g_sx[BROWS];
__device__ __nv_bfloat16  g_xhi[(size_t)BROWS * IN_DIM];
__device__ __nv_bfloat16  g_xlo[(size_t)BROWS * IN_DIM];

// ---------------------------------------------------------------------------
// W prep
// ---------------------------------------------------------------------------
__global__ __launch_bounds__(128) void wscale_kernel(const float* __restrict__ W) {
    __shared__ float red[128];
    int i = blockIdx.x, t = threadIdx.x;
    const float* wr = W + (size_t)i * OUT_DIM;
    float s = 0.f;
    for (int c = t; c < OUT_DIM; c += 128) { float v = wr[c]; s = fmaf(v, v, s); }
    red[t] = s;
    __syncthreads();
#pragma unroll
    for (int o = 64; o > 0; o >>= 1) { if (t < o) red[t] += red[t + o]; __syncthreads(); }
    if (t == 0) g_sw[i] = rsqrtf(fmaxf(red[0], 1e-12f));
}

__global__ __launch_bounds__(128) void wtrans_kernel(const float* __restrict__ W) {
    int n = blockIdx.x;
    for (int k = threadIdx.x; k < IN_DIM; k += 128) {
        float v = (n < OUT_DIM) ? W[(size_t)k * OUT_DIM + n] * g_sw[k] : 0.f;
        __nv_bfloat16 h = __float2bfloat16_rn(v);
        __nv_bfloat16 l = __float2bfloat16_rn(v - __bfloat162float(h));
        g_whiT[(size_t)n * IN_DIM + k] = h;
        g_wloT[(size_t)n * IN_DIM + k] = l;
    }
}

// ---------------------------------------------------------------------------
// x prep: one warp per row. Split fp32 -> bf16 hi/lo, fused sumsq -> g_sx.
// Lane covers k = lane*16 .. lane*16+15  (bf16x2 low half = even k).
// ---------------------------------------------------------------------------
__global__ __launch_bounds__(256) void xsplit_kernel(const float* __restrict__ x) {
    int row  = blockIdx.x * 8 + (threadIdx.x >> 5);
    int lane = threadIdx.x & 31;
    const float4* src = reinterpret_cast<const float4*>(x + (size_t)row * IN_DIM) + lane * 4;
    float4 v[4];
#pragma unroll
    for (int i = 0; i < 4; i++) v[i] = src[i];

    float s = 0.f;
#pragma unroll
    for (int i = 0; i < 4; i++) {
        s = fmaf(v[i].x, v[i].x, s); s = fmaf(v[i].y, v[i].y, s);
        s = fmaf(v[i].z, v[i].z, s); s = fmaf(v[i].w, v[i].w, s);
    }
#pragma unroll
    for (int o = 16; o > 0; o >>= 1) s += __shfl_xor_sync(0xffffffffu, s, o);
    if (lane == 0) g_sx[row] = rsqrtf(fmaxf(s, 1e-12f));

    uint32_t hu[8], lu[8];
#pragma unroll
    for (int i = 0; i < 4; i++) {
        hu[2*i]   = pack_hi(v[i].x, v[i].y);
        hu[2*i+1] = pack_hi(v[i].z, v[i].w);
        lu[2*i]   = pack_lo(v[i].x, v[i].y);
        lu[2*i+1] = pack_lo(v[i].z, v[i].w);
    }
    uint4* dhi = reinterpret_cast<uint4*>(g_xhi + (size_t)row * IN_DIM) + lane * 2;
    uint4* dlo = reinterpret_cast<uint4*>(g_xlo + (size_t)row * IN_DIM) + lane * 2;
    dhi[0] = make_uint4(hu[0], hu[1], hu[2], hu[3]);
    dhi[1] = make_uint4(hu[4], hu[5], hu[6], hu[7]);
    dlo[0] = make_uint4(lu[0], lu[1], lu[2], lu[3]);
    dlo[1] = make_uint4(lu[4], lu[5], lu[6], lu[7]);
}

// ---------------------------------------------------------------------------
// GEMM: CTA = 128 rows x 128 cols, K = 512 in 8 chunks of 64, 2-stage
// cp.async pipeline (A hi/lo + B hi/lo all bf16 from device scratch).
// ---------------------------------------------------------------------------
#define ST_AHI 0
#define ST_ALO 16384
#define ST_BHI 32768
#define ST_BLO 49152
#define ST_SIZE 65536
#define SM_TOTAL (2 * ST_SIZE)

__global__ __launch_bounds__(256, 1) void gemm_kernel(float* __restrict__ out) {
    extern __shared__ __align__(1024) unsigned char smem[];
    uint32_t sb = smem_u32(smem);
    const int tid  = threadIdx.x;
    const int lane = tid & 31;
    const int warp = tid >> 5;
    const int wm   = warp >> 1;          // 0..3
    const int wn   = warp & 1;           // 0..1
    const int n0   = blockIdx.x * 128;
    const int m0   = blockIdx.y * 128;

    float acc[2][8][4];
#pragma unroll
    for (int a = 0; a < 2; a++)
#pragma unroll
        for (int b = 0; b < 8; b++)
#pragma unroll
            for (int c = 0; c < 4; c++) acc[a][b][c] = 0.f;

    // A loader: thread t -> row t>>1, 64B half t&1  (4 x 16B per buffer)
    const int ar = tid >> 1, ah = tid & 1;
    const char* asrc_hi = reinterpret_cast<const char*>(g_xhi) + (size_t)(m0 + ar) * 1024 + ah * 64;
    const char* asrc_lo = reinterpret_cast<const char*>(g_xlo) + (size_t)(m0 + ar) * 1024 + ah * 64;
    const uint32_t a_row_base = (uint32_t)(ar * 128 + ah * 64);
    // B loader: thread t -> n row t&127, 64B half t>>7
    const int bn = tid & 127, bh2 = tid >> 7;
    const char* bsrc_hi = reinterpret_cast<const char*>(g_whiT) + (size_t)(n0 + bn) * 1024 + bh2 * 64;
    const char* bsrc_lo = reinterpret_cast<const char*>(g_wloT) + (size_t)(n0 + bn) * 1024 + bh2 * 64;
    const uint32_t b_row_base = (uint32_t)(bn * 128 + bh2 * 64);

#define LOAD_CHUNK(c, st) do {                                                  \
    uint32_t base = sb + (st) * ST_SIZE;                                        \
    _Pragma("unroll")                                                           \
    for (int j = 0; j < 4; j++) {                                               \
        CPA16(base + ST_AHI + SW128(a_row_base + j * 16), asrc_hi + (c) * 128 + j * 16); \
        CPA16(base + ST_ALO + SW128(a_row_base + j * 16), asrc_lo + (c) * 128 + j * 16); \
        CPA16(base + ST_BHI + SW128(b_row_base + j * 16), bsrc_hi + (c) * 128 + j * 16); \
        CPA16(base + ST_BLO + SW128(b_row_base + j * 16), bsrc_lo + (c) * 128 + j * 16); \
    } } while (0)

    LOAD_CHUNK(0, 0);
    CPA_COMMIT();

#pragma unroll 1
    for (int c = 0; c < 8; c++) {
        if (c < 7) {
            LOAD_CHUNK(c + 1, (c + 1) & 1);
            CPA_COMMIT();
            CPA_WAIT1();
        } else {
            CPA_WAIT0();
        }
        __syncthreads();

        const uint32_t base = sb + (c & 1) * ST_SIZE;
#pragma unroll
        for (int kk = 0; kk < 4; kk++) {
            uint32_t ahi[2][4], alo[2][4];
#pragma unroll
            for (int tm = 0; tm < 2; tm++) {
                uint32_t offa = SW128((uint32_t)((wm * 32 + tm * 16 + (lane & 15)) * 128
                                                 + kk * 32 + ((lane >> 4) << 4)));
                ldm_x4(ahi[tm], base + ST_AHI + offa);
                ldm_x4(alo[tm], base + ST_ALO + offa);
            }
#pragma unroll
            for (int nb = 0; nb < 4; nb++) {
                uint32_t offb = SW128((uint32_t)((wn * 64 + nb * 16 + (lane & 7) + ((lane >> 4) << 3)) * 128
                                                 + kk * 32 + (((lane >> 3) & 1) << 4)));
                uint32_t bh[4], bl[4];
                ldm_x4(bh, base + ST_BHI + offb);
                ldm_x4(bl, base + ST_BLO + offb);
#pragma unroll
                for (int tm = 0; tm < 2; tm++) {
                    mma_bf16(acc[tm][2*nb],   ahi[tm], bh);
                    mma_bf16(acc[tm][2*nb],   alo[tm], bh);
                    mma_bf16(acc[tm][2*nb],   ahi[tm], bl);
                    mma_bf16(acc[tm][2*nb+1], ahi[tm], bh + 2);
                    mma_bf16(acc[tm][2*nb+1], alo[tm], bh + 2);
                    mma_bf16(acc[tm][2*nb+1], ahi[tm], bl + 2);
                }
            }
        }
        __syncthreads();
    }

    // epilogue: scale by precomputed g_sx, predicated float2 stores
#pragma unroll
    for (int tm = 0; tm < 2; tm++) {
        int rl = wm * 32 + tm * 16 + (lane >> 2);
        float s0 = g_sx[m0 + rl];
        float s1 = g_sx[m0 + rl + 8];
        float* o0 = out + (size_t)(m0 + rl) * OUT_DIM;
        float* o1 = out + (size_t)(m0 + rl + 8) * OUT_DIM;
#pragma unroll
        for (int nt = 0; nt < 8; nt++) {
            int cg = n0 + wn * 64 + nt * 8 + (lane & 3) * 2;
            if (cg + 2 <= OUT_DIM) {
                float2 v0 = make_float2(acc[tm][nt][0] * s0, acc[tm][nt][1] * s0);
                float2 v1 = make_float2(acc[tm][nt][2] * s1, acc[tm][nt][3] * s1);
                *reinterpret_cast<float2*>(o0 + cg) = v0;
                *reinterpret_cast<float2*>(o1 + cg) = v1;
            }
        }
    }
}

// ---------------------------------------------------------------------------
extern "C" void kernel_launch(void* const* d_in, const int* in_sizes, int n_in,
                              void* d_out, int out_size) {
    const float* x = (const float*)d_in[0];
    const float* W = (const float*)d_in[1];
    if (in_sizes[0] == IN_DIM * OUT_DIM) { x = (const float*)d_in[1]; W = (const float*)d_in[0]; }
    float* out = (float*)d_out;

    cudaFuncSetAttribute(gemm_kernel, cudaFuncAttributeMaxDynamicSharedMemorySize, SM_TOTAL);

    wscale_kernel<<<IN_DIM, 128>>>(W);
    wtrans_kernel<<<IN_DIM, 128>>>(W);
    xsplit_kernel<<<BROWS / 8, 256>>>(x);
    dim3 grid(4, BROWS / 128);
    gemm_kernel<<<grid, 256, SM_TOTAL>>>(out);
}

// round 11
// speedup vs baseline: 1.2420x; 1.2420x over previous
#include <cuda_runtime.h>
#include <cuda_bf16.h>
#include <cstdint>

#define IN_DIM  512
#define OUT_DIM 462
#define BROWS   65536

// ---------------------------------------------------------------------------
// helpers
// ---------------------------------------------------------------------------
__device__ __forceinline__ uint32_t smem_u32(const void* p) {
    uint32_t a;
    asm("{ .reg .u64 t; cvta.to.shared.u64 t, %1; cvt.u32.u64 %0, t; }" : "=r"(a) : "l"(p));
    return a;
}

#define SW128(o) ((o) ^ (((o) >> 3) & 0x70))

#define CPA16(dst, src) \
    asm volatile("cp.async.cg.shared.global [%0], [%1], 16;" :: "r"(dst), "l"(src) : "memory")
#define CPA_COMMIT() asm volatile("cp.async.commit_group;" ::: "memory")
#define CPA_WAIT0()  asm volatile("cp.async.wait_group 0;" ::: "memory")
#define CPA_WAIT1()  asm volatile("cp.async.wait_group 1;" ::: "memory")

__device__ __forceinline__ void ldm_x4(uint32_t* r, uint32_t addr) {
    asm volatile("ldmatrix.sync.aligned.m8n8.x4.shared.b16 {%0,%1,%2,%3}, [%4];"
        : "=r"(r[0]), "=r"(r[1]), "=r"(r[2]), "=r"(r[3]) : "r"(addr));
}
__device__ __forceinline__ void mma_bf16(float* c, const uint32_t* a, const uint32_t* b) {
    asm volatile("mma.sync.aligned.m16n8k16.row.col.f32.bf16.bf16.f32 "
        "{%0,%1,%2,%3}, {%4,%5,%6,%7}, {%8,%9}, {%0,%1,%2,%3};"
        : "+f"(c[0]), "+f"(c[1]), "+f"(c[2]), "+f"(c[3])
        : "r"(a[0]), "r"(a[1]), "r"(a[2]), "r"(a[3]), "r"(b[0]), "r"(b[1]));
}

__device__ __forceinline__ uint32_t pack_hi(float a, float b) {
    __nv_bfloat162 p = __halves2bfloat162(__float2bfloat16_rn(a), __float2bfloat16_rn(b));
    return *reinterpret_cast<uint32_t*>(&p);
}
__device__ __forceinline__ uint32_t pack_lo(float a, float b) {
    __nv_bfloat16 ha = __float2bfloat16_rn(a), hb = __float2bfloat16_rn(b);
    __nv_bfloat162 p = __halves2bfloat162(
        __float2bfloat16_rn(a - __bfloat162float(ha)),
        __float2bfloat16_rn(b - __bfloat162float(hb)));
    return *reinterpret_cast<uint32_t*>(&p);
}

// ---------------------------------------------------------------------------
// Device scratch
// ---------------------------------------------------------------------------
__device__ float          g_sw[IN_DIM];
__device__ __nv_bfloat16  g_whiT[IN_DIM * IN_DIM];   // B[n][k], n>=462 zero
__device__ __nv_bfloat16  g_wloT[IN_DIM * IN_DIM];
__device__ float          g_sx[BROWS];
__device__ __nv_bfloat16  g_xhi[(size_t)BROWS * IN_DIM];
__device__ __nv_bfloat16  g_xlo[(size_t)BROWS * IN_DIM];

// ---------------------------------------------------------------------------
// W prep
// ---------------------------------------------------------------------------
__global__ __launch_bounds__(128) void wscale_kernel(const float* __restrict__ W) {
    __shared__ float red[128];
    int i = blockIdx.x, t = threadIdx.x;
    const float* wr = W + (size_t)i * OUT_DIM;
    float s = 0.f;
    for (int c = t; c < OUT_DIM; c += 128) { float v = wr[c]; s = fmaf(v, v, s); }
    red[t] = s;
    __syncthreads();
#pragma unroll
    for (int o = 64; o > 0; o >>= 1) { if (t < o) red[t] += red[t + o]; __syncthreads(); }
    if (t == 0) g_sw[i] = rsqrtf(fmaxf(red[0], 1e-12f));
}

__global__ __launch_bounds__(128) void wtrans_kernel(const float* __restrict__ W) {
    int n = blockIdx.x;
    for (int k = threadIdx.x; k < IN_DIM; k += 128) {
        float v = (n < OUT_DIM) ? W[(size_t)k * OUT_DIM + n] * g_sw[k] : 0.f;
        __nv_bfloat16 h = __float2bfloat16_rn(v);
        __nv_bfloat16 l = __float2bfloat16_rn(v - __bfloat162float(h));
        g_whiT[(size_t)n * IN_DIM + k] = h;
        g_wloT[(size_t)n * IN_DIM + k] = l;
    }
}

// ---------------------------------------------------------------------------
// x prep: one warp per row. Split fp32 -> bf16 hi/lo, fused sumsq -> g_sx.
// ---------------------------------------------------------------------------
__global__ __launch_bounds__(256) void xsplit_kernel(const float* __restrict__ x) {
    int row  = blockIdx.x * 8 + (threadIdx.x >> 5);
    int lane = threadIdx.x & 31;
    const float4* src = reinterpret_cast<const float4*>(x + (size_t)row * IN_DIM) + lane * 4;
    float4 v[4];
#pragma unroll
    for (int i = 0; i < 4; i++) v[i] = src[i];

    float s = 0.f;
#pragma unroll
    for (int i = 0; i < 4; i++) {
        s = fmaf(v[i].x, v[i].x, s); s = fmaf(v[i].y, v[i].y, s);
        s = fmaf(v[i].z, v[i].z, s); s = fmaf(v[i].w, v[i].w, s);
    }
#pragma unroll
    for (int o = 16; o > 0; o >>= 1) s += __shfl_xor_sync(0xffffffffu, s, o);
    if (lane == 0) g_sx[row] = rsqrtf(fmaxf(s, 1e-12f));

    uint32_t hu[8], lu[8];
#pragma unroll
    for (int i = 0; i < 4; i++) {
        hu[2*i]   = pack_hi(v[i].x, v[i].y);
        hu[2*i+1] = pack_hi(v[i].z, v[i].w);
        lu[2*i]   = pack_lo(v[i].x, v[i].y);
        lu[2*i+1] = pack_lo(v[i].z, v[i].w);
    }
    uint4* dhi = reinterpret_cast<uint4*>(g_xhi + (size_t)row * IN_DIM) + lane * 2;
    uint4* dlo = reinterpret_cast<uint4*>(g_xlo + (size_t)row * IN_DIM) + lane * 2;
    dhi[0] = make_uint4(hu[0], hu[1], hu[2], hu[3]);
    dhi[1] = make_uint4(hu[4], hu[5], hu[6], hu[7]);
    dlo[0] = make_uint4(lu[0], lu[1], lu[2], lu[3]);
    dlo[1] = make_uint4(lu[4], lu[5], lu[6], lu[7]);
}

// ---------------------------------------------------------------------------
// GEMM: CTA = 64 rows x 128 cols, K = 512 in 8 chunks of 64.
// 2-stage cp.async pipeline, 48KB/stage -> 96KB SMEM -> 2 CTAs/SM.
// 8 warps, warp tile 32x32 (wm: 2 m-slabs, wn: 4 n-slabs).
// ---------------------------------------------------------------------------
#define ST_AHI 0
#define ST_ALO 8192
#define ST_BHI 16384
#define ST_BLO 32768
#define ST_SIZE 49152
#define SM_TOTAL (2 * ST_SIZE)

__global__ __launch_bounds__(256, 2) void gemm_kernel(float* __restrict__ out) {
    extern __shared__ __align__(1024) unsigned char smem[];
    uint32_t sb = smem_u32(smem);
    const int tid  = threadIdx.x;
    const int lane = tid & 31;
    const int warp = tid >> 5;
    const int wm   = warp >> 2;          // 0..1  (32-row slab)
    const int wn   = warp & 3;           // 0..3  (32-col slab)
    const int n0   = blockIdx.x * 128;
    const int m0   = blockIdx.y * 64;

    float acc[2][4][4];
#pragma unroll
    for (int a = 0; a < 2; a++)
#pragma unroll
        for (int b = 0; b < 4; b++)
#pragma unroll
            for (int c = 0; c < 4; c++) acc[a][b][c] = 0.f;

    // A loader: thread t -> row t>>2 (0..63), 32B quarter (t&3); 2 x 16B per tile
    const int ar = tid >> 2;
    const int aq = (tid & 3) * 32;
    const char* asrc_hi = reinterpret_cast<const char*>(g_xhi) + (size_t)(m0 + ar) * 1024 + aq;
    const char* asrc_lo = reinterpret_cast<const char*>(g_xlo) + (size_t)(m0 + ar) * 1024 + aq;
    const uint32_t a_row_base = (uint32_t)(ar * 128 + aq);
    // B loader: thread t -> n row t>>1 (0..127), 64B half (t&1); 4 x 16B per tile
    const int bn = tid >> 1;
    const int bh2 = (tid & 1) * 64;
    const char* bsrc_hi = reinterpret_cast<const char*>(g_whiT) + (size_t)(n0 + bn) * 1024 + bh2;
    const char* bsrc_lo = reinterpret_cast<const char*>(g_wloT) + (size_t)(n0 + bn) * 1024 + bh2;
    const uint32_t b_row_base = (uint32_t)(bn * 128 + bh2);

#define LOAD_CHUNK(c, st) do {                                                  \
    uint32_t base = sb + (st) * ST_SIZE;                                        \
    _Pragma("unroll")                                                           \
    for (int j = 0; j < 2; j++) {                                               \
        CPA16(base + ST_AHI + SW128(a_row_base + j * 16), asrc_hi + (c) * 128 + j * 16); \
        CPA16(base + ST_ALO + SW128(a_row_base + j * 16), asrc_lo + (c) * 128 + j * 16); \
    }                                                                           \
    _Pragma("unroll")                                                           \
    for (int j = 0; j < 4; j++) {                                               \
        CPA16(base + ST_BHI + SW128(b_row_base + j * 16), bsrc_hi + (c) * 128 + j * 16); \
        CPA16(base + ST_BLO + SW128(b_row_base + j * 16), bsrc_lo + (c) * 128 + j * 16); \
    } } while (0)

    LOAD_CHUNK(0, 0);
    CPA_COMMIT();

#pragma unroll 1
    for (int c = 0; c < 8; c++) {
        if (c < 7) {
            LOAD_CHUNK(c + 1, (c + 1) & 1);
            CPA_COMMIT();
            CPA_WAIT1();
        } else {
            CPA_WAIT0();
        }
        __syncthreads();

        const uint32_t base = sb + (c & 1) * ST_SIZE;
#pragma unroll
        for (int kk = 0; kk < 4; kk++) {
            uint32_t ahi[2][4], alo[2][4];
#pragma unroll
            for (int tm = 0; tm < 2; tm++) {
                uint32_t offa = SW128((uint32_t)((wm * 32 + tm * 16 + (lane & 15)) * 128
                                                 + kk * 32 + ((lane >> 4) << 4)));
                ldm_x4(ahi[tm], base + ST_AHI + offa);
                ldm_x4(alo[tm], base + ST_ALO + offa);
            }
#pragma unroll
            for (int nb = 0; nb < 2; nb++) {
                uint32_t offb = SW128((uint32_t)((wn * 32 + nb * 16 + (lane & 7) + ((lane >> 4) << 3)) * 128
                                                 + kk * 32 + (((lane >> 3) & 1) << 4)));
                uint32_t bh[4], bl[4];
                ldm_x4(bh, base + ST_BHI + offb);
                ldm_x4(bl, base + ST_BLO + offb);
#pragma unroll
                for (int tm = 0; tm < 2; tm++) {
                    mma_bf16(acc[tm][2*nb],   ahi[tm], bh);
                    mma_bf16(acc[tm][2*nb],   alo[tm], bh);
                    mma_bf16(acc[tm][2*nb],   ahi[tm], bl);
                    mma_bf16(acc[tm][2*nb+1], ahi[tm], bh + 2);
                    mma_bf16(acc[tm][2*nb+1], alo[tm], bh + 2);
                    mma_bf16(acc[tm][2*nb+1], ahi[tm], bl + 2);
                }
            }
        }
        __syncthreads();
    }

    // epilogue: scale by precomputed g_sx, predicated float2 stores
#pragma unroll
    for (int tm = 0; tm < 2; tm++) {
        int rl = wm * 32 + tm * 16 + (lane >> 2);
        float s0 = g_sx[m0 + rl];
        float s1 = g_sx[m0 + rl + 8];
        float* o0 = out + (size_t)(m0 + rl) * OUT_DIM;
        float* o1 = out + (size_t)(m0 + rl + 8) * OUT_DIM;
#pragma unroll
        for (int nt = 0; nt < 4; nt++) {
            int cg = n0 + wn * 32 + (nt >> 1) * 16 + (nt & 1) * 8 + (lane & 3) * 2;
            if (cg + 2 <= OUT_DIM) {
                float2 v0 = make_float2(acc[tm][nt][0] * s0, acc[tm][nt][1] * s0);
                float2 v1 = make_float2(acc[tm][nt][2] * s1, acc[tm][nt][3] * s1);
                *reinterpret_cast<float2*>(o0 + cg) = v0;
                *reinterpret_cast<float2*>(o1 + cg) = v1;
            }
        }
    }
}

// ---------------------------------------------------------------------------
extern "C" void kernel_launch(void* const* d_in, const int* in_sizes, int n_in,
                              void* d_out, int out_size) {
    const float* x = (const float*)d_in[0];
    const float* W = (const float*)d_in[1];
    if (in_sizes[0] == IN_DIM * OUT_DIM) { x = (const float*)d_in[1]; W = (const float*)d_in[0]; }
    float* out = (float*)d_out;

    cudaFuncSetAttribute(gemm_kernel, cudaFuncAttributeMaxDynamicSharedMemorySize, SM_TOTAL);

    wscale_kernel<<<IN_DIM, 128>>>(W);
    wtrans_kernel<<<IN_DIM, 128>>>(W);
    xsplit_kernel<<<BROWS / 8, 256>>>(x);
    dim3 grid(4, BROWS / 64);
    gemm_kernel<<<grid, 256, SM_TOTAL>>>(out);
}

// round 14
// speedup vs baseline: 2.4415x; 1.9658x over previous
#include <cuda_runtime.h>
#include <cuda_fp16.h>
#include <cstdint>

#define IN_DIM  512
#define OUT_DIM 462
#define BROWS   65536

// ---------------------------------------------------------------------------
// helpers
// ---------------------------------------------------------------------------
__device__ __forceinline__ uint32_t smem_u32(const void* p) {
    uint32_t a;
    asm("{ .reg .u64 t; cvta.to.shared.u64 t, %1; cvt.u32.u64 %0, t; }" : "=r"(a) : "l"(p));
    return a;
}

#define SW128(o) ((o) ^ (((o) >> 3) & 0x70))

#define CPA16(dst, src) \
    asm volatile("cp.async.cg.shared.global [%0], [%1], 16;" :: "r"(dst), "l"(src) : "memory")
#define CPA_COMMIT() asm volatile("cp.async.commit_group;" ::: "memory")
#define CPA_WAIT0()  asm volatile("cp.async.wait_group 0;" ::: "memory")
#define CPA_WAIT1()  asm volatile("cp.async.wait_group 1;" ::: "memory")

__device__ __forceinline__ void ldm_x4(uint32_t* r, uint32_t addr) {
    asm volatile("ldmatrix.sync.aligned.m8n8.x4.shared.b16 {%0,%1,%2,%3}, [%4];"
        : "=r"(r[0]), "=r"(r[1]), "=r"(r[2]), "=r"(r[3]) : "r"(addr));
}
__device__ __forceinline__ void mma_fp16(float* c, const uint32_t* a, const uint32_t* b) {
    asm volatile("mma.sync.aligned.m16n8k16.row.col.f32.f16.f16.f32 "
        "{%0,%1,%2,%3}, {%4,%5,%6,%7}, {%8,%9}, {%0,%1,%2,%3};"
        : "+f"(c[0]), "+f"(c[1]), "+f"(c[2]), "+f"(c[3])
        : "r"(a[0]), "r"(a[1]), "r"(a[2]), "r"(a[3]), "r"(b[0]), "r"(b[1]));
}

__device__ __forceinline__ uint32_t pack_h2(float a, float b) {
    __half2 p = __floats2half2_rn(a, b);   // a = low element (even k)
    return *reinterpret_cast<uint32_t*>(&p);
}

// ---------------------------------------------------------------------------
// Device scratch
// ---------------------------------------------------------------------------
__device__ float   g_sw[IN_DIM];
__device__ __half  g_wh[IN_DIM * IN_DIM];            // B[n][k], n>=462 zero
__device__ float   g_sx[BROWS];
__device__ __half  g_xh[(size_t)BROWS * IN_DIM];

// ---------------------------------------------------------------------------
// W prep
// ---------------------------------------------------------------------------
__global__ __launch_bounds__(128) void wscale_kernel(const float* __restrict__ W) {
    __shared__ float red[128];
    int i = blockIdx.x, t = threadIdx.x;
    const float* wr = W + (size_t)i * OUT_DIM;
    float s = 0.f;
    for (int c = t; c < OUT_DIM; c += 128) { float v = wr[c]; s = fmaf(v, v, s); }
    red[t] = s;
    __syncthreads();
#pragma unroll
    for (int o = 64; o > 0; o >>= 1) { if (t < o) red[t] += red[t + o]; __syncthreads(); }
    if (t == 0) g_sw[i] = rsqrtf(fmaxf(red[0], 1e-12f));
}

__global__ __launch_bounds__(128) void wtrans_kernel(const float* __restrict__ W) {
    int n = blockIdx.x;
    for (int k = threadIdx.x; k < IN_DIM; k += 128) {
        float v = (n < OUT_DIM) ? W[(size_t)k * OUT_DIM + n] * g_sw[k] : 0.f;
        g_wh[(size_t)n * IN_DIM + k] = __float2half_rn(v);
    }
}

// ---------------------------------------------------------------------------
// x prep: one warp per row. fp32 -> fp16, fused sumsq -> g_sx.
// ---------------------------------------------------------------------------
__global__ __launch_bounds__(256) void xsplit_kernel(const float* __restrict__ x) {
    int row  = blockIdx.x * 8 + (threadIdx.x >> 5);
    int lane = threadIdx.x & 31;
    const float4* src = reinterpret_cast<const float4*>(x + (size_t)row * IN_DIM) + lane * 4;
    float4 v[4];
#pragma unroll
    for (int i = 0; i < 4; i++) v[i] = src[i];

    float s = 0.f;
#pragma unroll
    for (int i = 0; i < 4; i++) {
        s = fmaf(v[i].x, v[i].x, s); s = fmaf(v[i].y, v[i].y, s);
        s = fmaf(v[i].z, v[i].z, s); s = fmaf(v[i].w, v[i].w, s);
    }
#pragma unroll
    for (int o = 16; o > 0; o >>= 1) s += __shfl_xor_sync(0xffffffffu, s, o);
    if (lane == 0) g_sx[row] = rsqrtf(fmaxf(s, 1e-12f));

    uint32_t hu[8];
#pragma unroll
    for (int i = 0; i < 4; i++) {
        hu[2*i]   = pack_h2(v[i].x, v[i].y);
        hu[2*i+1] = pack_h2(v[i].z, v[i].w);
    }
    uint4* dst = reinterpret_cast<uint4*>(g_xh + (size_t)row * IN_DIM) + lane * 2;
    dst[0] = make_uint4(hu[0], hu[1], hu[2], hu[3]);
    dst[1] = make_uint4(hu[4], hu[5], hu[6], hu[7]);
}

// ---------------------------------------------------------------------------
// GEMM: CTA = 64 rows x 128 cols, K = 512 in 8 chunks of 64.
// Single fp16 term, 2-stage cp.async pipeline, 24KB/stage -> 48KB SMEM.
// 8 warps, warp tile 32x32. 3 CTAs/SM.
// ---------------------------------------------------------------------------
#define ST_A 0
#define ST_B 8192
#define ST_SIZE 24576
#define SM_TOTAL (2 * ST_SIZE)

__global__ __launch_bounds__(256, 3) void gemm_kernel(float* __restrict__ out) {
    extern __shared__ __align__(1024) unsigned char smem[];
    uint32_t sb = smem_u32(smem);
    const int tid  = threadIdx.x;
    const int lane = tid & 31;
    const int warp = tid >> 5;
    const int wm   = warp >> 2;          // 0..1  (32-row slab)
    const int wn   = warp & 3;           // 0..3  (32-col slab)
    const int n0   = blockIdx.x * 128;
    const int m0   = blockIdx.y * 64;

    float acc[2][4][4];
#pragma unroll
    for (int a = 0; a < 2; a++)
#pragma unroll
        for (int b = 0; b < 4; b++)
#pragma unroll
            for (int c = 0; c < 4; c++) acc[a][b][c] = 0.f;

    // A loader: thread t -> row t>>2 (0..63), 32B quarter (t&3); 2 x 16B per tile
    const int ar = tid >> 2;
    const int aq = (tid & 3) * 32;
    const char* asrc = reinterpret_cast<const char*>(g_xh) + (size_t)(m0 + ar) * 1024 + aq;
    const uint32_t a_row_base = (uint32_t)(ar * 128 + aq);
    // B loader: thread t -> n row t>>1 (0..127), 64B half (t&1); 4 x 16B per tile
    const int bn = tid >> 1;
    const int bh2 = (tid & 1) * 64;
    const char* bsrc = reinterpret_cast<const char*>(g_wh) + (size_t)(n0 + bn) * 1024 + bh2;
    const uint32_t b_row_base = (uint32_t)(bn * 128 + bh2);

#define LOAD_CHUNK(c, st) do {                                                  \
    uint32_t base = sb + (st) * ST_SIZE;                                        \
    _Pragma("unroll")                                                           \
    for (int j = 0; j < 2; j++)                                                 \
        CPA16(base + ST_A + SW128(a_row_base + j * 16), asrc + (c) * 128 + j * 16); \
    _Pragma("unroll")                                                           \
    for (int j = 0; j < 4; j++)                                                 \
        CPA16(base + ST_B + SW128(b_row_base + j * 16), bsrc + (c) * 128 + j * 16); \
    } while (0)

    LOAD_CHUNK(0, 0);
    CPA_COMMIT();

#pragma unroll 1
    for (int c = 0; c < 8; c++) {
        if (c < 7) {
            LOAD_CHUNK(c + 1, (c + 1) & 1);
            CPA_COMMIT();
            CPA_WAIT1();
        } else {
            CPA_WAIT0();
        }
        __syncthreads();

        const uint32_t base = sb + (c & 1) * ST_SIZE;
#pragma unroll
        for (int kk = 0; kk < 4; kk++) {
            uint32_t af[2][4];
#pragma unroll
            for (int tm = 0; tm < 2; tm++) {
                uint32_t offa = SW128((uint32_t)((wm * 32 + tm * 16 + (lane & 15)) * 128
                                                 + kk * 32 + ((lane >> 4) << 4)));
                ldm_x4(af[tm], base + ST_A + offa);
            }
#pragma unroll
            for (int nb = 0; nb < 2; nb++) {
                uint32_t offb = SW128((uint32_t)((wn * 32 + nb * 16 + (lane & 7) + ((lane >> 4) << 3)) * 128
                                                 + kk * 32 + (((lane >> 3) & 1) << 4)));
                uint32_t bf[4];
                ldm_x4(bf, base + ST_B + offb);
#pragma unroll
                for (int tm = 0; tm < 2; tm++) {
                    mma_fp16(acc[tm][2*nb],   af[tm], bf);
                    mma_fp16(acc[tm][2*nb+1], af[tm], bf + 2);
                }
            }
        }
        __syncthreads();
    }

    // epilogue: scale by precomputed g_sx, predicated float2 stores
#pragma unroll
    for (int tm = 0; tm < 2; tm++) {
        int rl = wm * 32 + tm * 16 + (lane >> 2);
        float s0 = g_sx[m0 + rl];
        float s1 = g_sx[m0 + rl + 8];
        float* o0 = out + (size_t)(m0 + rl) * OUT_DIM;
        float* o1 = out + (size_t)(m0 + rl + 8) * OUT_DIM;
#pragma unroll
        for (int nt = 0; nt < 4; nt++) {
            int cg = n0 + wn * 32 + (nt >> 1) * 16 + (nt & 1) * 8 + (lane & 3) * 2;
            if (cg + 2 <= OUT_DIM) {
                float2 v0 = make_float2(acc[tm][nt][0] * s0, acc[tm][nt][1] * s0);
                float2 v1 = make_float2(acc[tm][nt][2] * s1, acc[tm][nt][3] * s1);
                *reinterpret_cast<float2*>(o0 + cg) = v0;
                *reinterpret_cast<float2*>(o1 + cg) = v1;
            }
        }
    }
}

// ---------------------------------------------------------------------------
extern "C" void kernel_launch(void* const* d_in, const int* in_sizes, int n_in,
                              void* d_out, int out_size) {
    const float* x = (const float*)d_in[0];
    const float* W = (const float*)d_in[1];
    if (in_sizes[0] == IN_DIM * OUT_DIM) { x = (const float*)d_in[1]; W = (const float*)d_in[0]; }
    float* out = (float*)d_out;

    cudaFuncSetAttribute(gemm_kernel, cudaFuncAttributeMaxDynamicSharedMemorySize, SM_TOTAL);

    wscale_kernel<<<IN_DIM, 128>>>(W);
    wtrans_kernel<<<IN_DIM, 128>>>(W);
    xsplit_kernel<<<BROWS / 8, 256>>>(x);
    dim3 grid(4, BROWS / 64);
    gemm_kernel<<<grid, 256, SM_TOTAL>>>(out);
}

// round 15
// speedup vs baseline: 2.6091x; 1.0686x over previous
#include <cuda_runtime.h>
#include <cuda_fp16.h>
#include <cstdint>

#define IN_DIM  512
#define OUT_DIM 462
#define BROWS   65536

// ---------------------------------------------------------------------------
// helpers
// ---------------------------------------------------------------------------
__device__ __forceinline__ uint32_t smem_u32(const void* p) {
    uint32_t a;
    asm("{ .reg .u64 t; cvta.to.shared.u64 t, %1; cvt.u32.u64 %0, t; }" : "=r"(a) : "l"(p));
    return a;
}

#define SW128(o) ((o) ^ (((o) >> 3) & 0x70))

#define CPA16(dst, src) \
    asm volatile("cp.async.cg.shared.global [%0], [%1], 16;" :: "r"(dst), "l"(src) : "memory")
#define CPA_COMMIT() asm volatile("cp.async.commit_group;" ::: "memory")
#define CPA_WAIT0()  asm volatile("cp.async.wait_group 0;" ::: "memory")
#define CPA_WAIT1()  asm volatile("cp.async.wait_group 1;" ::: "memory")

__device__ __forceinline__ void ldm_x4(uint32_t* r, uint32_t addr) {
    asm volatile("ldmatrix.sync.aligned.m8n8.x4.shared.b16 {%0,%1,%2,%3}, [%4];"
        : "=r"(r[0]), "=r"(r[1]), "=r"(r[2]), "=r"(r[3]) : "r"(addr));
}
__device__ __forceinline__ void mma_fp16(float* c, const uint32_t* a, const uint32_t* b) {
    asm volatile("mma.sync.aligned.m16n8k16.row.col.f32.f16.f16.f32 "
        "{%0,%1,%2,%3}, {%4,%5,%6,%7}, {%8,%9}, {%0,%1,%2,%3};"
        : "+f"(c[0]), "+f"(c[1]), "+f"(c[2]), "+f"(c[3])
        : "r"(a[0]), "r"(a[1]), "r"(a[2]), "r"(a[3]), "r"(b[0]), "r"(b[1]));
}

__device__ __forceinline__ uint32_t pack_h2(float a, float b) {
    __half2 p = __floats2half2_rn(a, b);   // a = low element (even k)
    return *reinterpret_cast<uint32_t*>(&p);
}

// ---------------------------------------------------------------------------
// Device scratch
// ---------------------------------------------------------------------------
__device__ float   g_sw[IN_DIM];
__device__ __half  g_wh[IN_DIM * IN_DIM];            // B[n][k], n>=462 zero
__device__ float   g_sx[BROWS];
__device__ __half  g_xh[(size_t)BROWS * IN_DIM];

// ---------------------------------------------------------------------------
// W prep
// ---------------------------------------------------------------------------
__global__ __launch_bounds__(128) void wscale_kernel(const float* __restrict__ W) {
    __shared__ float red[128];
    int i = blockIdx.x, t = threadIdx.x;
    const float* wr = W + (size_t)i * OUT_DIM;
    float s = 0.f;
    for (int c = t; c < OUT_DIM; c += 128) { float v = wr[c]; s = fmaf(v, v, s); }
    red[t] = s;
    __syncthreads();
#pragma unroll
    for (int o = 64; o > 0; o >>= 1) { if (t < o) red[t] += red[t + o]; __syncthreads(); }
    if (t == 0) g_sw[i] = rsqrtf(fmaxf(red[0], 1e-12f));
}

__global__ __launch_bounds__(128) void wtrans_kernel(const float* __restrict__ W) {
    int n = blockIdx.x;
    for (int k = threadIdx.x; k < IN_DIM; k += 128) {
        float v = (n < OUT_DIM) ? W[(size_t)k * OUT_DIM + n] * g_sw[k] : 0.f;
        g_wh[(size_t)n * IN_DIM + k] = __float2half_rn(v);
    }
}

// ---------------------------------------------------------------------------
// x prep: one warp per row. fp32 -> fp16, fused sumsq -> g_sx.
// ---------------------------------------------------------------------------
__global__ __launch_bounds__(256) void xsplit_kernel(const float* __restrict__ x) {
    int row  = blockIdx.x * 8 + (threadIdx.x >> 5);
    int lane = threadIdx.x & 31;
    const float4* src = reinterpret_cast<const float4*>(x + (size_t)row * IN_DIM) + lane * 4;
    float4 v[4];
#pragma unroll
    for (int i = 0; i < 4; i++) v[i] = src[i];

    float s = 0.f;
#pragma unroll
    for (int i = 0; i < 4; i++) {
        s = fmaf(v[i].x, v[i].x, s); s = fmaf(v[i].y, v[i].y, s);
        s = fmaf(v[i].z, v[i].z, s); s = fmaf(v[i].w, v[i].w, s);
    }
#pragma unroll
    for (int o = 16; o > 0; o >>= 1) s += __shfl_xor_sync(0xffffffffu, s, o);
    if (lane == 0) g_sx[row] = rsqrtf(fmaxf(s, 1e-12f));

    uint32_t hu[8];
#pragma unroll
    for (int i = 0; i < 4; i++) {
        hu[2*i]   = pack_h2(v[i].x, v[i].y);
        hu[2*i+1] = pack_h2(v[i].z, v[i].w);
    }
    uint4* dst = reinterpret_cast<uint4*>(g_xh + (size_t)row * IN_DIM) + lane * 2;
    dst[0] = make_uint4(hu[0], hu[1], hu[2], hu[3]);
    dst[1] = make_uint4(hu[4], hu[5], hu[6], hu[7]);
}

// ---------------------------------------------------------------------------
// GEMM: CTA = 128 rows x 128 cols, K = 512 in 8 chunks of 64.
// Warp tile 64x32 (2 wm x 4 wn), single fp16 term, 2-stage cp.async,
// 32KB/stage -> 64KB SMEM -> 2 CTAs/SM.
// ---------------------------------------------------------------------------
#define ST_A 0
#define ST_B 16384
#define ST_SIZE 32768
#define SM_TOTAL (2 * ST_SIZE)

__global__ __launch_bounds__(256, 2) void gemm_kernel(float* __restrict__ out) {
    extern __shared__ __align__(1024) unsigned char smem[];
    uint32_t sb = smem_u32(smem);
    const int tid  = threadIdx.x;
    const int lane = tid & 31;
    const int warp = tid >> 5;
    const int wm   = warp >> 2;          // 0..1  (64-row slab)
    const int wn   = warp & 3;           // 0..3  (32-col slab)
    const int n0   = blockIdx.x * 128;
    const int m0   = blockIdx.y * 128;

    float acc[4][4][4];
#pragma unroll
    for (int a = 0; a < 4; a++)
#pragma unroll
        for (int b = 0; b < 4; b++)
#pragma unroll
            for (int c = 0; c < 4; c++) acc[a][b][c] = 0.f;

    // A loader: thread t -> row t>>1 (0..127), 64B half (t&1); 4 x 16B per tile
    const int ar = tid >> 1;
    const int aq = (tid & 1) * 64;
    const char* asrc = reinterpret_cast<const char*>(g_xh) + (size_t)(m0 + ar) * 1024 + aq;
    const uint32_t a_row_base = (uint32_t)(ar * 128 + aq);
    // B loader: thread t -> n row t>>1 (0..127), 64B half (t&1); 4 x 16B per tile
    const int bn = tid >> 1;
    const int bh2 = (tid & 1) * 64;
    const char* bsrc = reinterpret_cast<const char*>(g_wh) + (size_t)(n0 + bn) * 1024 + bh2;
    const uint32_t b_row_base = (uint32_t)(bn * 128 + bh2);

#define LOAD_CHUNK(c, st) do {                                                  \
    uint32_t base = sb + (st) * ST_SIZE;                                        \
    _Pragma("unroll")                                                           \
    for (int j = 0; j < 4; j++)                                                 \
        CPA16(base + ST_A + SW128(a_row_base + j * 16), asrc + (c) * 128 + j * 16); \
    _Pragma("unroll")                                                           \
    for (int j = 0; j < 4; j++)                                                 \
        CPA16(base + ST_B + SW128(b_row_base + j * 16), bsrc + (c) * 128 + j * 16); \
    } while (0)

    LOAD_CHUNK(0, 0);
    CPA_COMMIT();

#pragma unroll 1
    for (int c = 0; c < 8; c++) {
        if (c < 7) {
            LOAD_CHUNK(c + 1, (c + 1) & 1);
            CPA_COMMIT();
            CPA_WAIT1();
        } else {
            CPA_WAIT0();
        }
        __syncthreads();

        const uint32_t base = sb + (c & 1) * ST_SIZE;
#pragma unroll
        for (int kk = 0; kk < 4; kk++) {
            uint32_t af[4][4];
#pragma unroll
            for (int tm = 0; tm < 4; tm++) {
                uint32_t offa = SW128((uint32_t)((wm * 64 + tm * 16 + (lane & 15)) * 128
                                                 + kk * 32 + ((lane >> 4) << 4)));
                ldm_x4(af[tm], base + ST_A + offa);
            }
#pragma unroll
            for (int nb = 0; nb < 2; nb++) {
                uint32_t offb = SW128((uint32_t)((wn * 32 + nb * 16 + (lane & 7) + ((lane >> 4) << 3)) * 128
                                                 + kk * 32 + (((lane >> 3) & 1) << 4)));
                uint32_t bf[4];
                ldm_x4(bf, base + ST_B + offb);
#pragma unroll
                for (int tm = 0; tm < 4; tm++) {
                    mma_fp16(acc[tm][2*nb],   af[tm], bf);
                    mma_fp16(acc[tm][2*nb+1], af[tm], bf + 2);
                }
            }
        }
        __syncthreads();
    }

    // epilogue: scale by precomputed g_sx, predicated float2 stores
#pragma unroll
    for (int tm = 0; tm < 4; tm++) {
        int rl = wm * 64 + tm * 16 + (lane >> 2);
        float s0 = g_sx[m0 + rl];
        float s1 = g_sx[m0 + rl + 8];
        float* o0 = out + (size_t)(m0 + rl) * OUT_DIM;
        float* o1 = out + (size_t)(m0 + rl + 8) * OUT_DIM;
#pragma unroll
        for (int nt = 0; nt < 4; nt++) {
            int cg = n0 + wn * 32 + (nt >> 1) * 16 + (nt & 1) * 8 + (lane & 3) * 2;
            if (cg + 2 <= OUT_DIM) {
                float2 v0 = make_float2(acc[tm][nt][0] * s0, acc[tm][nt][1] * s0);
                float2 v1 = make_float2(acc[tm][nt][2] * s1, acc[tm][nt][3] * s1);
                *reinterpret_cast<float2*>(o0 + cg) = v0;
                *reinterpret_cast<float2*>(o1 + cg) = v1;
            }
        }
    }
}

// ---------------------------------------------------------------------------
extern "C" void kernel_launch(void* const* d_in, const int* in_sizes, int n_in,
                              void* d_out, int out_size) {
    const float* x = (const float*)d_in[0];
    const float* W = (const float*)d_in[1];
    if (in_sizes[0] == IN_DIM * OUT_DIM) { x = (const float*)d_in[1]; W = (const float*)d_in[0]; }
    float* out = (float*)d_out;

    cudaFuncSetAttribute(gemm_kernel, cudaFuncAttributeMaxDynamicSharedMemorySize, SM_TOTAL);

    wscale_kernel<<<IN_DIM, 128>>>(W);
    wtrans_kernel<<<IN_DIM, 128>>>(W);
    xsplit_kernel<<<BROWS / 8, 256>>>(x);
    dim3 grid(4, BROWS / 128);
    gemm_kernel<<<grid, 256, SM_TOTAL>>>(out);
}

// round 16
// speedup vs baseline: 2.6624x; 1.0204x over previous
#include <cuda_runtime.h>
#include <cuda_fp16.h>
#include <cstdint>

#define IN_DIM  512
#define OUT_DIM 462
#define BROWS   65536

// ---------------------------------------------------------------------------
// helpers
// ---------------------------------------------------------------------------
__device__ __forceinline__ uint32_t smem_u32(const void* p) {
    uint32_t a;
    asm("{ .reg .u64 t; cvta.to.shared.u64 t, %1; cvt.u32.u64 %0, t; }" : "=r"(a) : "l"(p));
    return a;
}

#define SW128(o) ((o) ^ (((o) >> 3) & 0x70))

#define CPA16(dst, src) \
    asm volatile("cp.async.cg.shared.global [%0], [%1], 16;" :: "r"(dst), "l"(src) : "memory")
#define CPA_COMMIT() asm volatile("cp.async.commit_group;" ::: "memory")
#define CPA_WAIT0()  asm volatile("cp.async.wait_group 0;" ::: "memory")
#define CPA_WAIT1()  asm volatile("cp.async.wait_group 1;" ::: "memory")

__device__ __forceinline__ void ldm_x4(uint32_t* r, uint32_t addr) {
    asm volatile("ldmatrix.sync.aligned.m8n8.x4.shared.b16 {%0,%1,%2,%3}, [%4];"
        : "=r"(r[0]), "=r"(r[1]), "=r"(r[2]), "=r"(r[3]) : "r"(addr));
}
__device__ __forceinline__ void mma_fp16(float* c, const uint32_t* a, const uint32_t* b) {
    asm volatile("mma.sync.aligned.m16n8k16.row.col.f32.f16.f16.f32 "
        "{%0,%1,%2,%3}, {%4,%5,%6,%7}, {%8,%9}, {%0,%1,%2,%3};"
        : "+f"(c[0]), "+f"(c[1]), "+f"(c[2]), "+f"(c[3])
        : "r"(a[0]), "r"(a[1]), "r"(a[2]), "r"(a[3]), "r"(b[0]), "r"(b[1]));
}

__device__ __forceinline__ uint32_t pack_h2(float a, float b) {
    __half2 p = __floats2half2_rn(a, b);   // a = low element (even k)
    return *reinterpret_cast<uint32_t*>(&p);
}

// ---------------------------------------------------------------------------
// Device scratch
// ---------------------------------------------------------------------------
__device__ float   g_sw[IN_DIM];
__device__ __half  g_wh[IN_DIM * IN_DIM];            // B[n][k], n>=462 zero
__device__ float   g_sx[BROWS];
__device__ __half  g_xh[(size_t)BROWS * IN_DIM];

// ---------------------------------------------------------------------------
// W prep
// ---------------------------------------------------------------------------
__global__ __launch_bounds__(128) void wscale_kernel(const float* __restrict__ W) {
    __shared__ float red[128];
    int i = blockIdx.x, t = threadIdx.x;
    const float* wr = W + (size_t)i * OUT_DIM;
    float s = 0.f;
    for (int c = t; c < OUT_DIM; c += 128) { float v = wr[c]; s = fmaf(v, v, s); }
    red[t] = s;
    __syncthreads();
#pragma unroll
    for (int o = 64; o > 0; o >>= 1) { if (t < o) red[t] += red[t + o]; __syncthreads(); }
    if (t == 0) g_sw[i] = rsqrtf(fmaxf(red[0], 1e-12f));
}

__global__ __launch_bounds__(128) void wtrans_kernel(const float* __restrict__ W) {
    int n = blockIdx.x;
    for (int k = threadIdx.x; k < IN_DIM; k += 128) {
        float v = (n < OUT_DIM) ? W[(size_t)k * OUT_DIM + n] * g_sw[k] : 0.f;
        g_wh[(size_t)n * IN_DIM + k] = __float2half_rn(v);
    }
}

// ---------------------------------------------------------------------------
// x prep: one warp per row. fp32 -> fp16, fused sumsq -> g_sx.
// ---------------------------------------------------------------------------
__global__ __launch_bounds__(256) void xsplit_kernel(const float* __restrict__ x) {
    int row  = blockIdx.x * 8 + (threadIdx.x >> 5);
    int lane = threadIdx.x & 31;
    const float4* src = reinterpret_cast<const float4*>(x + (size_t)row * IN_DIM) + lane * 4;
    float4 v[4];
#pragma unroll
    for (int i = 0; i < 4; i++) v[i] = src[i];

    float s = 0.f;
#pragma unroll
    for (int i = 0; i < 4; i++) {
        s = fmaf(v[i].x, v[i].x, s); s = fmaf(v[i].y, v[i].y, s);
        s = fmaf(v[i].z, v[i].z, s); s = fmaf(v[i].w, v[i].w, s);
    }
#pragma unroll
    for (int o = 16; o > 0; o >>= 1) s += __shfl_xor_sync(0xffffffffu, s, o);
    if (lane == 0) g_sx[row] = rsqrtf(fmaxf(s, 1e-12f));

    uint32_t hu[8];
#pragma unroll
    for (int i = 0; i < 4; i++) {
        hu[2*i]   = pack_h2(v[i].x, v[i].y);
        hu[2*i+1] = pack_h2(v[i].z, v[i].w);
    }
    uint4* dst = reinterpret_cast<uint4*>(g_xh + (size_t)row * IN_DIM) + lane * 2;
    dst[0] = make_uint4(hu[0], hu[1], hu[2], hu[3]);
    dst[1] = make_uint4(hu[4], hu[5], hu[6], hu[7]);
}

// ---------------------------------------------------------------------------
// GEMM: CTA = 128 rows x 128 cols, K = 512 in 8 chunks of 64.
// Warp tile 64x32 (2 wm x 4 wn), single fp16 term.
// 3-stage cp.async pipeline, ONE __syncthreads per chunk.
// 32KB/stage -> 96KB SMEM -> 2 CTAs/SM.
// ---------------------------------------------------------------------------
#define ST_A 0
#define ST_B 16384
#define ST_SIZE 32768
#define SM_TOTAL (3 * ST_SIZE)

__global__ __launch_bounds__(256, 2) void gemm_kernel(float* __restrict__ out) {
    extern __shared__ __align__(1024) unsigned char smem[];
    uint32_t sb = smem_u32(smem);
    const int tid  = threadIdx.x;
    const int lane = tid & 31;
    const int warp = tid >> 5;
    const int wm   = warp >> 2;          // 0..1  (64-row slab)
    const int wn   = warp & 3;           // 0..3  (32-col slab)
    const int n0   = blockIdx.x * 128;
    const int m0   = blockIdx.y * 128;

    float acc[4][4][4];
#pragma unroll
    for (int a = 0; a < 4; a++)
#pragma unroll
        for (int b = 0; b < 4; b++)
#pragma unroll
            for (int c = 0; c < 4; c++) acc[a][b][c] = 0.f;

    // A loader: thread t -> row t>>1 (0..127), 64B half (t&1); 4 x 16B per tile
    const int ar = tid >> 1;
    const int aq = (tid & 1) * 64;
    const char* asrc = reinterpret_cast<const char*>(g_xh) + (size_t)(m0 + ar) * 1024 + aq;
    const uint32_t a_row_base = (uint32_t)(ar * 128 + aq);
    // B loader: thread t -> n row t>>1 (0..127), 64B half (t&1); 4 x 16B per tile
    const int bn = tid >> 1;
    const int bh2 = (tid & 1) * 64;
    const char* bsrc = reinterpret_cast<const char*>(g_wh) + (size_t)(n0 + bn) * 1024 + bh2;
    const uint32_t b_row_base = (uint32_t)(bn * 128 + bh2);

#define LOAD_CHUNK(c, st) do {                                                  \
    uint32_t base = sb + (st) * ST_SIZE;                                        \
    _Pragma("unroll")                                                           \
    for (int j = 0; j < 4; j++)                                                 \
        CPA16(base + ST_A + SW128(a_row_base + j * 16), asrc + (c) * 128 + j * 16); \
    _Pragma("unroll")                                                           \
    for (int j = 0; j < 4; j++)                                                 \
        CPA16(base + ST_B + SW128(b_row_base + j * 16), bsrc + (c) * 128 + j * 16); \
    } while (0)

    // prologue: 2 chunks in flight
    LOAD_CHUNK(0, 0);
    CPA_COMMIT();
    LOAD_CHUNK(1, 1);
    CPA_COMMIT();

    int s_comp = 0;   // stage holding chunk c
    int s_load = 2;   // stage to load chunk c+2 into

#pragma unroll 1
    for (int c = 0; c < 8; c++) {
        // wait for chunk c's cp.async groups (this thread's oldest group)
        if (c < 7) CPA_WAIT1(); else CPA_WAIT0();
        // ONE barrier: (a) chunk c visible to all warps, (b) all warps done
        // reading stage s_load (they read it as chunk c-1 before this point)
        __syncthreads();
        if (c < 6) {
            LOAD_CHUNK(c + 2, s_load);
            CPA_COMMIT();
        }

        const uint32_t base = sb + s_comp * ST_SIZE;
#pragma unroll
        for (int kk = 0; kk < 4; kk++) {
            uint32_t af[4][4];
#pragma unroll
            for (int tm = 0; tm < 4; tm++) {
                uint32_t offa = SW128((uint32_t)((wm * 64 + tm * 16 + (lane & 15)) * 128
                                                 + kk * 32 + ((lane >> 4) << 4)));
                ldm_x4(af[tm], base + ST_A + offa);
            }
#pragma unroll
            for (int nb = 0; nb < 2; nb++) {
                uint32_t offb = SW128((uint32_t)((wn * 32 + nb * 16 + (lane & 7) + ((lane >> 4) << 3)) * 128
                                                 + kk * 32 + (((lane >> 3) & 1) << 4)));
                uint32_t bf[4];
                ldm_x4(bf, base + ST_B + offb);
#pragma unroll
                for (int tm = 0; tm < 4; tm++) {
                    mma_fp16(acc[tm][2*nb],   af[tm], bf);
                    mma_fp16(acc[tm][2*nb+1], af[tm], bf + 2);
                }
            }
        }

        s_comp = (s_comp == 2) ? 0 : s_comp + 1;
        s_load = (s_load == 2) ? 0 : s_load + 1;
    }

    // epilogue: scale by precomputed g_sx, predicated float2 stores
#pragma unroll
    for (int tm = 0; tm < 4; tm++) {
        int rl = wm * 64 + tm * 16 + (lane >> 2);
        float s0 = g_sx[m0 + rl];
        float s1 = g_sx[m0 + rl + 8];
        float* o0 = out + (size_t)(m0 + rl) * OUT_DIM;
        float* o1 = out + (size_t)(m0 + rl + 8) * OUT_DIM;
#pragma unroll
        for (int nt = 0; nt < 4; nt++) {
            int cg = n0 + wn * 32 + (nt >> 1) * 16 + (nt & 1) * 8 + (lane & 3) * 2;
            if (cg + 2 <= OUT_DIM) {
                float2 v0 = make_float2(acc[tm][nt][0] * s0, acc[tm][nt][1] * s0);
                float2 v1 = make_float2(acc[tm][nt][2] * s1, acc[tm][nt][3] * s1);
                *reinterpret_cast<float2*>(o0 + cg) = v0;
                *reinterpret_cast<float2*>(o1 + cg) = v1;
            }
        }
    }
}

// ---------------------------------------------------------------------------
extern "C" void kernel_launch(void* const* d_in, const int* in_sizes, int n_in,
                              void* d_out, int out_size) {
    const float* x = (const float*)d_in[0];
    const float* W = (const float*)d_in[1];
    if (in_sizes[0] == IN_DIM * OUT_DIM) { x = (const float*)d_in[1]; W = (const float*)d_in[0]; }
    float* out = (float*)d_out;

    cudaFuncSetAttribute(gemm_kernel, cudaFuncAttributeMaxDynamicSharedMemorySize, SM_TOTAL);

    wscale_kernel<<<IN_DIM, 128>>>(W);
    wtrans_kernel<<<IN_DIM, 128>>>(W);
    xsplit_kernel<<<BROWS / 8, 256>>>(x);
    dim3 grid(4, BROWS / 128);
    gemm_kernel<<<grid, 256, SM_TOTAL>>>(out);
}